// round 15
// baseline (speedup 1.0000x reference)
#include <cuda_runtime.h>
#include <cuda_fp16.h>
#include <cstdint>

#define NN 50000
#define DD 64
#define MAXE 1600000
#define SCAN_B 256
#define NBLK ((NN + SCAN_B - 1) / SCAN_B)

// Scratch (device globals; no allocations allowed)
__device__ __align__(16) float g_agg[NN * DD];     // normalized mean-agg buffer (fp32)
__device__ __align__(16) float g_h[NN * DD];       // layer-0 output (fp32, self term)
__device__ __align__(16) __half g_in16[NN * DD];   // fp16 gather copy (x, then h)
__device__ int g_is64;                             // edge-index dtype flag
__device__ int g_deg[NN];                          // in-degree (by dst)
__device__ int g_rowptr[NN];                       // CSR row starts (block-partial)
__device__ int g_col[MAXE];                        // CSR column (src) indices
__device__ int g_src[MAXE];                        // decoded int32 src
__device__ int g_dst[MAXE];                        // decoded int32 dst
__device__ int g_rank[MAXE];                       // within-bucket rank per edge
__device__ int g_bsum[NBLK];                       // scan block sums
__device__ int g_bpre[NBLK];                       // exclusive prefix of block sums
__device__ int g_ticket;                           // last-block detector for scan1
// B fragments in tf32 hi/lo, fragment order: [kt][ks][ntile][lane] -> (bh0,bh1,bl0,bl1)
__device__ __align__(16) uint4 g_Bf0[2 * 8 * 8 * 32];
__device__ __align__(16) uint4 g_Bf1[2 * 8 * 8 * 32];

__device__ __forceinline__ uint32_t f2tf32(float f) {
    uint32_t r;
    asm("cvt.rna.tf32.f32 %0, %1;" : "=r"(r) : "f"(f));
    return r;
}

// prep B fragments + zero deg + reset ticket + dtype detect + x -> fp16 copy
__global__ void setup_kernel(const float* __restrict__ Wl0, const float* __restrict__ Wr0,
                             const float* __restrict__ Wl1, const float* __restrict__ Wr1,
                             const long long* __restrict__ ei,
                             const float* __restrict__ x) {
    int i = blockIdx.x * blockDim.x + threadIdx.x;
    if (i == 0) {
        long long acc = 0;
#pragma unroll
        for (int k = 0; k < 8; k++) acc |= (ei[k] >> 32);
        g_is64 = (acc == 0) ? 1 : 0;
        g_ticket = 0;
    }
    if (i < 2 * 8 * 8 * 32) {
        int lane = i & 31;
        int ntg = (i >> 5) & 7;
        int ks = (i >> 8) & 7;
        int kt = i >> 11;
        int t4 = lane & 3;
        int g = lane >> 2;
        int n = ntg * 8 + g;
        int k0 = kt * 64 + ks * 8 + t4;   // 0..127
        int k1 = k0 + 4;
        float w0a = (k0 < DD) ? Wl0[n * DD + k0] : Wr0[n * DD + (k0 - DD)];
        float w1a = (k1 < DD) ? Wl0[n * DD + k1] : Wr0[n * DD + (k1 - DD)];
        float w0b = (k0 < DD) ? Wl1[n * DD + k0] : Wr1[n * DD + (k0 - DD)];
        float w1b = (k1 < DD) ? Wl1[n * DD + k1] : Wr1[n * DD + (k1 - DD)];
        uint32_t h0, h1;
        h0 = f2tf32(w0a); h1 = f2tf32(w1a);
        g_Bf0[i] = make_uint4(h0, h1, f2tf32(w0a - __uint_as_float(h0)),
                                       f2tf32(w1a - __uint_as_float(h1)));
        h0 = f2tf32(w0b); h1 = f2tf32(w1b);
        g_Bf1[i] = make_uint4(h0, h1, f2tf32(w0b - __uint_as_float(h0)),
                                       f2tf32(w1b - __uint_as_float(h1)));
    }
    if (i < NN) g_deg[i] = 0;
    // convert x to fp16: thread i handles 8 floats
    if (i < NN * DD / 8) {
        const float4* p = reinterpret_cast<const float4*>(x) + i * 2;
        float4 a = __ldg(p);
        float4 b = __ldg(p + 1);
        __half2 h0 = __float22half2_rn(make_float2(a.x, a.y));
        __half2 h1 = __float22half2_rn(make_float2(a.z, a.w));
        __half2 h2 = __float22half2_rn(make_float2(b.x, b.y));
        __half2 h3 = __float22half2_rn(make_float2(b.z, b.w));
        uint4 o;
        o.x = *reinterpret_cast<uint32_t*>(&h0);
        o.y = *reinterpret_cast<uint32_t*>(&h1);
        o.z = *reinterpret_cast<uint32_t*>(&h2);
        o.w = *reinterpret_cast<uint32_t*>(&h3);
        *(reinterpret_cast<uint4*>(g_in16) + i) = o;
    }
}

// Decode edge list to int32 + degree histogram + within-bucket rank (R13 scalar).
__global__ void convert_count(const void* __restrict__ ei_raw, int E) {
    int e = blockIdx.x * blockDim.x + threadIdx.x;
    if (e >= E) return;
    int s, d;
    if (g_is64) {
        const long long* ei = (const long long*)ei_raw;
        s = (int)ei[e];
        d = (int)ei[E + e];
    } else {
        const int* ei = (const int*)ei_raw;
        s = ei[e];
        d = ei[E + e];
    }
    g_src[e] = s;
    g_dst[e] = d;
    g_rank[e] = atomicAdd(&g_deg[d], 1);
}

// scan: per-block exclusive scan + block sums; last block scans block sums.
__global__ void scan1() {
    __shared__ int sh[SCAN_B];
    int i = blockIdx.x * SCAN_B + threadIdx.x;
    int v = (i < NN) ? g_deg[i] : 0;
    sh[threadIdx.x] = v;
    __syncthreads();
#pragma unroll
    for (int off = 1; off < SCAN_B; off <<= 1) {
        int t = (threadIdx.x >= off) ? sh[threadIdx.x - off] : 0;
        __syncthreads();
        sh[threadIdx.x] += t;
        __syncthreads();
    }
    int incl = sh[threadIdx.x];
    if (i < NN) g_rowptr[i] = incl - v;
    if (threadIdx.x == SCAN_B - 1) g_bsum[blockIdx.x] = incl;

    __threadfence();
    __shared__ int isLast;
    if (threadIdx.x == 0)
        isLast = (atomicAdd(&g_ticket, 1) == gridDim.x - 1) ? 1 : 0;
    __syncthreads();
    if (isLast) {
        int bv = (threadIdx.x < NBLK) ? g_bsum[threadIdx.x] : 0;
        sh[threadIdx.x] = bv;
        __syncthreads();
#pragma unroll
        for (int off = 1; off < SCAN_B; off <<= 1) {
            int t = (threadIdx.x >= off) ? sh[threadIdx.x - off] : 0;
            __syncthreads();
            sh[threadIdx.x] += t;
            __syncthreads();
        }
        if (threadIdx.x < NBLK) g_bpre[threadIdx.x] = sh[threadIdx.x] - bv;
    }
}

// CSR fill: atomic-free via precomputed ranks (R13 scalar).
__global__ void fill_csr(int E) {
    int e = blockIdx.x * blockDim.x + threadIdx.x;
    if (e >= E) return;
    int d = g_dst[e];
    g_col[g_rowptr[d] + g_bpre[d >> 8] + g_rank[e]] = g_src[e];
}

// load 4 halves (8B) -> float4
__device__ __forceinline__ float4 ldg_h4(const __half* p) {
    uint2 u = __ldg(reinterpret_cast<const uint2*>(p));
    __half2 a = *reinterpret_cast<__half2*>(&u.x);
    __half2 b = *reinterpret_cast<__half2*>(&u.y);
    float2 fa = __half22float2(a);
    float2 fb = __half22float2(b);
    return make_float4(fa.x, fa.y, fb.x, fb.y);
}

// ---- pull aggregation from fp16 copy: 16 threads per node, atomic-free ----
// Lane handles 4 features (8 bytes); 16 lanes cover the full 128B fp16 row.
__global__ void aggregate() {
    int gid = blockIdx.x * blockDim.x + threadIdx.x;
    int node = gid >> 4;
    int lane = gid & 15;
    if (node >= NN) return;

    int beg = g_rowptr[node] + g_bpre[node >> 8];
    int deg = g_deg[node];

    float4 acc = make_float4(0.f, 0.f, 0.f, 0.f);
    int j = 0;
    for (; j + 4 <= deg; j += 4) {
        int i0 = __ldg(g_col + beg + j + 0);
        int i1 = __ldg(g_col + beg + j + 1);
        int i2 = __ldg(g_col + beg + j + 2);
        int i3 = __ldg(g_col + beg + j + 3);
        float4 v0 = ldg_h4(g_in16 + (size_t)i0 * DD + lane * 4);
        float4 v1 = ldg_h4(g_in16 + (size_t)i1 * DD + lane * 4);
        float4 v2 = ldg_h4(g_in16 + (size_t)i2 * DD + lane * 4);
        float4 v3 = ldg_h4(g_in16 + (size_t)i3 * DD + lane * 4);
        acc.x += v0.x; acc.y += v0.y; acc.z += v0.z; acc.w += v0.w;
        acc.x += v1.x; acc.y += v1.y; acc.z += v1.z; acc.w += v1.w;
        acc.x += v2.x; acc.y += v2.y; acc.z += v2.z; acc.w += v2.w;
        acc.x += v3.x; acc.y += v3.y; acc.z += v3.z; acc.w += v3.w;
    }
    for (; j < deg; j++) {
        int i0 = __ldg(g_col + beg + j);
        float4 v0 = ldg_h4(g_in16 + (size_t)i0 * DD + lane * 4);
        acc.x += v0.x; acc.y += v0.y; acc.z += v0.z; acc.w += v0.w;
    }
    float sc = 1.f / (float)max(deg, 1);
    acc.x *= sc; acc.y *= sc; acc.z *= sc; acc.w *= sc;
    reinterpret_cast<float4*>(g_agg + (size_t)node * DD)[lane] = acc;
}

__device__ __forceinline__ void mma_tf32(float c[4], uint32_t a0, uint32_t a1,
                                         uint32_t a2, uint32_t a3,
                                         uint32_t b0, uint32_t b1) {
    asm volatile(
        "mma.sync.aligned.m16n8k8.row.col.f32.tf32.tf32.f32 "
        "{%0,%1,%2,%3}, {%4,%5,%6,%7}, {%8,%9}, {%0,%1,%2,%3};"
        : "+f"(c[0]), "+f"(c[1]), "+f"(c[2]), "+f"(c[3])
        : "r"(a0), "r"(a1), "r"(a2), "r"(a3), "r"(b0), "r"(b1));
}

// Fused: C[64 nodes][64 out] = A[64][128] * B[128][64] + bias (+ ReLU)
// 3xTF32 (R11 form). When writeH: also writes fp16 copy of h into g_in16
// for layer-1's gather.
#define SA_S 68
__global__ __launch_bounds__(256) void gemm_combine(const float* __restrict__ x,
                                                    int useH, int useW1,
                                                    const float* __restrict__ bias,
                                                    float* __restrict__ dout,
                                                    int writeH, int doRelu) {
    __shared__ __align__(16) uint32_t sAh[64 * SA_S];
    __shared__ __align__(16) uint32_t sAl[64 * SA_S];
    const float* xin = useH ? g_h : x;
    const uint4* Bf = useW1 ? g_Bf1 : g_Bf0;
    float* outp = writeH ? g_h : dout;

    int t = threadIdx.x;
    int m0 = blockIdx.x * 64;
    int wid = t >> 5;
    int lane = t & 31;
    int wm = wid >> 1;
    int wn = wid & 1;
    int g = lane >> 2;
    int t4 = lane & 3;

    float c[4][4];
#pragma unroll
    for (int i = 0; i < 4; i++)
#pragma unroll
        for (int j = 0; j < 4; j++) c[i][j] = 0.f;

    int lm = t >> 2;
    int lq = t & 3;
    int node_l = m0 + lm;

#pragma unroll
    for (int kt = 0; kt < 2; kt++) {
        {
            const float* srcRow = (kt == 0) ? (g_agg + (size_t)node_l * DD)
                                            : (xin + (size_t)node_l * DD);
#pragma unroll
            for (int f = 0; f < 4; f++) {
                float4 v = make_float4(0.f, 0.f, 0.f, 0.f);
                if (node_l < NN)
                    v = *reinterpret_cast<const float4*>(srcRow + lq * 16 + f * 4);
                uint4 h, l;
                h.x = f2tf32(v.x); l.x = f2tf32(v.x - __uint_as_float(h.x));
                h.y = f2tf32(v.y); l.y = f2tf32(v.y - __uint_as_float(h.y));
                h.z = f2tf32(v.z); l.z = f2tf32(v.z - __uint_as_float(h.z));
                h.w = f2tf32(v.w); l.w = f2tf32(v.w - __uint_as_float(h.w));
                int o = lm * SA_S + lq * 16 + f * 4;
                *reinterpret_cast<uint4*>(sAh + o) = h;
                *reinterpret_cast<uint4*>(sAl + o) = l;
            }
        }
        __syncthreads();

#pragma unroll
        for (int ks = 0; ks < 8; ks++) {
            int kk = ks * 8;
            const uint32_t* Ah = sAh + (wm * 16 + g) * SA_S + kk + t4;
            const uint32_t* Al = sAl + (wm * 16 + g) * SA_S + kk + t4;
            uint32_t ah0 = Ah[0], ah1 = Ah[8 * SA_S], ah2 = Ah[4], ah3 = Ah[8 * SA_S + 4];
            uint32_t al0 = Al[0], al1 = Al[8 * SA_S], al2 = Al[4], al3 = Al[8 * SA_S + 4];

            const uint4* Brow = Bf + ((kt * 8 + ks) * 8 + wn * 4) * 32 + lane;
#pragma unroll
            for (int nt = 0; nt < 4; nt++) {
                uint4 b = __ldg(Brow + nt * 32);
                mma_tf32(c[nt], ah0, ah1, ah2, ah3, b.x, b.y);
                mma_tf32(c[nt], ah0, ah1, ah2, ah3, b.z, b.w);
                mma_tf32(c[nt], al0, al1, al2, al3, b.x, b.y);
            }
        }
        __syncthreads();
    }

    // Epilogue: c0 (row=g, col=t4*2), c1 (col+1), c2 (row+8), c3 (row+8,col+1).
#pragma unroll
    for (int nt = 0; nt < 4; nt++) {
        int col = wn * 32 + nt * 8 + t4 * 2;
        float b0 = bias[col];
        float b1 = bias[col + 1];
        int row0 = m0 + wm * 16 + g;
        int row1 = row0 + 8;
        float2 o0 = make_float2(c[nt][0] + b0, c[nt][1] + b1);
        float2 o1 = make_float2(c[nt][2] + b0, c[nt][3] + b1);
        if (doRelu) {
            o0.x = fmaxf(o0.x, 0.f); o0.y = fmaxf(o0.y, 0.f);
            o1.x = fmaxf(o1.x, 0.f); o1.y = fmaxf(o1.y, 0.f);
        }
        if (row0 < NN) {
            *reinterpret_cast<float2*>(outp + (size_t)row0 * DD + col) = o0;
            if (writeH) {
                __half2 hh = __float22half2_rn(o0);
                *reinterpret_cast<__half2*>(g_in16 + (size_t)row0 * DD + col) = hh;
            }
        }
        if (row1 < NN) {
            *reinterpret_cast<float2*>(outp + (size_t)row1 * DD + col) = o1;
            if (writeH) {
                __half2 hh = __float22half2_rn(o1);
                *reinterpret_cast<__half2*>(g_in16 + (size_t)row1 * DD + col) = hh;
            }
        }
    }
}

extern "C" void kernel_launch(void* const* d_in, const int* in_sizes, int n_in,
                              void* d_out, int out_size) {
    const float* x        = (const float*)d_in[0];
    const void* ei        = d_in[1];
    const float* Wl0      = (const float*)d_in[2];
    const float* bl0      = (const float*)d_in[3];
    const float* Wr0      = (const float*)d_in[4];
    const float* Wl1      = (const float*)d_in[5];
    const float* bl1      = (const float*)d_in[6];
    const float* Wr1      = (const float*)d_in[7];
    float* out = (float*)d_out;

    int E = in_sizes[1] / 2;

    int edgeBlocks = (E + 255) / 256;
    int aggBlocks = (NN * 16 + 255) / 256;
    int gemmBlocks = (NN + 63) / 64;
    int setupBlocks = (NN * DD / 8 + 255) / 256;   // covers conversion (largest role)

    setup_kernel<<<setupBlocks, 256>>>(Wl0, Wr0, Wl1, Wr1, (const long long*)ei, x);

    // CSR build (shared by both layers)
    convert_count<<<edgeBlocks, 256>>>(ei, E);
    scan1<<<NBLK, SCAN_B>>>();
    fill_csr<<<edgeBlocks, 256>>>(E);

    // Layer 0
    aggregate<<<aggBlocks, 256>>>();
    gemm_combine<<<gemmBlocks, 256>>>(x, /*useH=*/0, /*useW1=*/0, bl0, out,
                                      /*writeH=*/1, /*doRelu=*/1);

    // Layer 1
    aggregate<<<aggBlocks, 256>>>();
    gemm_combine<<<gemmBlocks, 256>>>(x, /*useH=*/1, /*useW1=*/1, bl1, out,
                                      /*writeH=*/0, /*doRelu=*/0);
}

// round 16
// speedup vs baseline: 1.0658x; 1.0658x over previous
#include <cuda_runtime.h>
#include <cstdint>

#define NN 50000
#define DD 64
#define MAXE 1600000
#define SCAN_B 256
#define NBLK ((NN + SCAN_B - 1) / SCAN_B)

// Scratch (device globals; no allocations allowed)
__device__ __align__(16) float g_agg[NN * DD];     // normalized mean-agg buffer
__device__ __align__(16) float g_h[NN * DD];       // layer-0 output
__device__ int g_is64;                             // edge-index dtype flag
__device__ int g_deg[NN];                          // in-degree (by dst)
__device__ int g_rowptr[NN];                       // CSR row starts (block-partial)
__device__ int g_col[MAXE];                        // CSR column (src) indices
__device__ int g_src[MAXE];                        // decoded int32 src
__device__ int g_dst[MAXE];                        // decoded int32 dst
__device__ int g_rank[MAXE];                       // within-bucket rank per edge
__device__ int g_bsum[NBLK];                       // scan block sums
__device__ int g_bpre[NBLK];                       // exclusive prefix of block sums
__device__ int g_ticket;                           // last-block detector for scan1
// B fragments in tf32 hi/lo, fragment order: [kt][ks][ntile][lane] -> (bh0,bh1,bl0,bl1)
__device__ __align__(16) uint4 g_Bf0[2 * 8 * 8 * 32];
__device__ __align__(16) uint4 g_Bf1[2 * 8 * 8 * 32];

__device__ __forceinline__ uint32_t f2tf32(float f) {
    uint32_t r;
    asm("cvt.rna.tf32.f32 %0, %1;" : "=r"(r) : "f"(f));
    return r;
}

// prep B fragments + zero degree counters + reset scan ticket + dtype detect
__global__ void setup_kernel(const float* __restrict__ Wl0, const float* __restrict__ Wr0,
                             const float* __restrict__ Wl1, const float* __restrict__ Wr1,
                             const long long* __restrict__ ei) {
    int i = blockIdx.x * blockDim.x + threadIdx.x;
    if (i == 0) {
        long long acc = 0;
#pragma unroll
        for (int k = 0; k < 8; k++) acc |= (ei[k] >> 32);
        g_is64 = (acc == 0) ? 1 : 0;
        g_ticket = 0;
    }
    if (i < 2 * 8 * 8 * 32) {
        int lane = i & 31;
        int ntg = (i >> 5) & 7;
        int ks = (i >> 8) & 7;
        int kt = i >> 11;
        int t4 = lane & 3;
        int g = lane >> 2;
        int n = ntg * 8 + g;
        int k0 = kt * 64 + ks * 8 + t4;   // 0..127
        int k1 = k0 + 4;
        float w0a = (k0 < DD) ? Wl0[n * DD + k0] : Wr0[n * DD + (k0 - DD)];
        float w1a = (k1 < DD) ? Wl0[n * DD + k1] : Wr0[n * DD + (k1 - DD)];
        float w0b = (k0 < DD) ? Wl1[n * DD + k0] : Wr1[n * DD + (k0 - DD)];
        float w1b = (k1 < DD) ? Wl1[n * DD + k1] : Wr1[n * DD + (k1 - DD)];
        uint32_t h0, h1;
        h0 = f2tf32(w0a); h1 = f2tf32(w1a);
        g_Bf0[i] = make_uint4(h0, h1, f2tf32(w0a - __uint_as_float(h0)),
                                       f2tf32(w1a - __uint_as_float(h1)));
        h0 = f2tf32(w0b); h1 = f2tf32(w1b);
        g_Bf1[i] = make_uint4(h0, h1, f2tf32(w0b - __uint_as_float(h0)),
                                       f2tf32(w1b - __uint_as_float(h1)));
    }
    if (i < NN) g_deg[i] = 0;
}

// Decode edge list to int32 + degree histogram + within-bucket rank (scalar).
__global__ void convert_count(const void* __restrict__ ei_raw, int E) {
    int e = blockIdx.x * blockDim.x + threadIdx.x;
    if (e >= E) return;
    int s, d;
    if (g_is64) {
        const long long* ei = (const long long*)ei_raw;
        s = (int)ei[e];
        d = (int)ei[E + e];
    } else {
        const int* ei = (const int*)ei_raw;
        s = ei[e];
        d = ei[E + e];
    }
    g_src[e] = s;
    g_dst[e] = d;
    g_rank[e] = atomicAdd(&g_deg[d], 1);
}

// scan: per-block exclusive scan + block sums; last block scans block sums.
__global__ void scan1() {
    __shared__ int sh[SCAN_B];
    int i = blockIdx.x * SCAN_B + threadIdx.x;
    int v = (i < NN) ? g_deg[i] : 0;
    sh[threadIdx.x] = v;
    __syncthreads();
#pragma unroll
    for (int off = 1; off < SCAN_B; off <<= 1) {
        int t = (threadIdx.x >= off) ? sh[threadIdx.x - off] : 0;
        __syncthreads();
        sh[threadIdx.x] += t;
        __syncthreads();
    }
    int incl = sh[threadIdx.x];
    if (i < NN) g_rowptr[i] = incl - v;
    if (threadIdx.x == SCAN_B - 1) g_bsum[blockIdx.x] = incl;

    __threadfence();
    __shared__ int isLast;
    if (threadIdx.x == 0)
        isLast = (atomicAdd(&g_ticket, 1) == gridDim.x - 1) ? 1 : 0;
    __syncthreads();
    if (isLast) {
        int bv = (threadIdx.x < NBLK) ? g_bsum[threadIdx.x] : 0;
        sh[threadIdx.x] = bv;
        __syncthreads();
#pragma unroll
        for (int off = 1; off < SCAN_B; off <<= 1) {
            int t = (threadIdx.x >= off) ? sh[threadIdx.x - off] : 0;
            __syncthreads();
            sh[threadIdx.x] += t;
            __syncthreads();
        }
        if (threadIdx.x < NBLK) g_bpre[threadIdx.x] = sh[threadIdx.x] - bv;
    }
}

// CSR fill: atomic-free via precomputed ranks (scalar).
__global__ void fill_csr(int E) {
    int e = blockIdx.x * blockDim.x + threadIdx.x;
    if (e >= E) return;
    int d = g_dst[e];
    g_col[g_rowptr[d] + g_bpre[d >> 8] + g_rank[e]] = g_src[e];
}

// ---- pull-style aggregation: 16 threads per node, atomic-free ----
// Software-pipelined: next iteration's 4 column indices are prefetched while
// the current gathers are in flight, overlapping the two L2-latency legs.
__global__ void aggregate(const float* __restrict__ x, int useH) {
    int gid = blockIdx.x * blockDim.x + threadIdx.x;
    int node = gid >> 4;
    int lane = gid & 15;
    if (node >= NN) return;
    const float* xin = useH ? g_h : x;

    int beg = g_rowptr[node] + g_bpre[node >> 8];
    int deg = g_deg[node];

    float4 acc = make_float4(0.f, 0.f, 0.f, 0.f);
    int j = 0;
    if (deg >= 4) {
        // preload first index quad
        int i0 = __ldg(g_col + beg + 0);
        int i1 = __ldg(g_col + beg + 1);
        int i2 = __ldg(g_col + beg + 2);
        int i3 = __ldg(g_col + beg + 3);
        for (; j + 8 <= deg; j += 4) {
            // issue gathers for current quad
            float4 v0 = __ldg(reinterpret_cast<const float4*>(xin + (size_t)i0 * DD) + lane);
            float4 v1 = __ldg(reinterpret_cast<const float4*>(xin + (size_t)i1 * DD) + lane);
            float4 v2 = __ldg(reinterpret_cast<const float4*>(xin + (size_t)i2 * DD) + lane);
            float4 v3 = __ldg(reinterpret_cast<const float4*>(xin + (size_t)i3 * DD) + lane);
            // prefetch next quad's indices (overlaps with gathers)
            i0 = __ldg(g_col + beg + j + 4);
            i1 = __ldg(g_col + beg + j + 5);
            i2 = __ldg(g_col + beg + j + 6);
            i3 = __ldg(g_col + beg + j + 7);
            acc.x += v0.x; acc.y += v0.y; acc.z += v0.z; acc.w += v0.w;
            acc.x += v1.x; acc.y += v1.y; acc.z += v1.z; acc.w += v1.w;
            acc.x += v2.x; acc.y += v2.y; acc.z += v2.z; acc.w += v2.w;
            acc.x += v3.x; acc.y += v3.y; acc.z += v3.z; acc.w += v3.w;
        }
        // drain the in-flight quad
        {
            float4 v0 = __ldg(reinterpret_cast<const float4*>(xin + (size_t)i0 * DD) + lane);
            float4 v1 = __ldg(reinterpret_cast<const float4*>(xin + (size_t)i1 * DD) + lane);
            float4 v2 = __ldg(reinterpret_cast<const float4*>(xin + (size_t)i2 * DD) + lane);
            float4 v3 = __ldg(reinterpret_cast<const float4*>(xin + (size_t)i3 * DD) + lane);
            acc.x += v0.x; acc.y += v0.y; acc.z += v0.z; acc.w += v0.w;
            acc.x += v1.x; acc.y += v1.y; acc.z += v1.z; acc.w += v1.w;
            acc.x += v2.x; acc.y += v2.y; acc.z += v2.z; acc.w += v2.w;
            acc.x += v3.x; acc.y += v3.y; acc.z += v3.z; acc.w += v3.w;
            j += 4;
        }
    }
    for (; j < deg; j++) {
        int i0 = __ldg(g_col + beg + j);
        float4 v0 = __ldg(reinterpret_cast<const float4*>(xin + (size_t)i0 * DD) + lane);
        acc.x += v0.x; acc.y += v0.y; acc.z += v0.z; acc.w += v0.w;
    }
    float sc = 1.f / (float)max(deg, 1);
    acc.x *= sc; acc.y *= sc; acc.z *= sc; acc.w *= sc;
    reinterpret_cast<float4*>(g_agg + (size_t)node * DD)[lane] = acc;
}

__device__ __forceinline__ void mma_tf32(float c[4], uint32_t a0, uint32_t a1,
                                         uint32_t a2, uint32_t a3,
                                         uint32_t b0, uint32_t b1) {
    asm volatile(
        "mma.sync.aligned.m16n8k8.row.col.f32.tf32.tf32.f32 "
        "{%0,%1,%2,%3}, {%4,%5,%6,%7}, {%8,%9}, {%0,%1,%2,%3};"
        : "+f"(c[0]), "+f"(c[1]), "+f"(c[2]), "+f"(c[3])
        : "r"(a0), "r"(a1), "r"(a2), "r"(a3), "r"(b0), "r"(b1));
}

// Fused: C[64 nodes][64 out] = A[64][128] * B[128][64] + bias (+ ReLU)
// 3xTF32; A pre-split to hi/lo smem at load; B fragments pre-split in global
// fragment order -> inner loop: 8 LDS + 4 LDG.128 + 12 MMA per k-step.
#define SA_S 68
__global__ __launch_bounds__(256) void gemm_combine(const float* __restrict__ x,
                                                    int useH, int useW1,
                                                    const float* __restrict__ bias,
                                                    float* __restrict__ dout,
                                                    int writeH, int doRelu) {
    __shared__ __align__(16) uint32_t sAh[64 * SA_S];
    __shared__ __align__(16) uint32_t sAl[64 * SA_S];
    const float* xin = useH ? g_h : x;
    const uint4* Bf = useW1 ? g_Bf1 : g_Bf0;
    float* outp = writeH ? g_h : dout;

    int t = threadIdx.x;
    int m0 = blockIdx.x * 64;
    int wid = t >> 5;
    int lane = t & 31;
    int wm = wid >> 1;
    int wn = wid & 1;
    int g = lane >> 2;
    int t4 = lane & 3;

    float c[4][4];
#pragma unroll
    for (int i = 0; i < 4; i++)
#pragma unroll
        for (int j = 0; j < 4; j++) c[i][j] = 0.f;

    int lm = t >> 2;
    int lq = t & 3;
    int node_l = m0 + lm;

#pragma unroll
    for (int kt = 0; kt < 2; kt++) {
        {
            const float* srcRow = (kt == 0) ? (g_agg + (size_t)node_l * DD)
                                            : (xin + (size_t)node_l * DD);
#pragma unroll
            for (int f = 0; f < 4; f++) {
                float4 v = make_float4(0.f, 0.f, 0.f, 0.f);
                if (node_l < NN)
                    v = *reinterpret_cast<const float4*>(srcRow + lq * 16 + f * 4);
                uint4 h, l;
                h.x = f2tf32(v.x); l.x = f2tf32(v.x - __uint_as_float(h.x));
                h.y = f2tf32(v.y); l.y = f2tf32(v.y - __uint_as_float(h.y));
                h.z = f2tf32(v.z); l.z = f2tf32(v.z - __uint_as_float(h.z));
                h.w = f2tf32(v.w); l.w = f2tf32(v.w - __uint_as_float(h.w));
                int o = lm * SA_S + lq * 16 + f * 4;
                *reinterpret_cast<uint4*>(sAh + o) = h;
                *reinterpret_cast<uint4*>(sAl + o) = l;
            }
        }
        __syncthreads();

#pragma unroll
        for (int ks = 0; ks < 8; ks++) {
            int kk = ks * 8;
            const uint32_t* Ah = sAh + (wm * 16 + g) * SA_S + kk + t4;
            const uint32_t* Al = sAl + (wm * 16 + g) * SA_S + kk + t4;
            uint32_t ah0 = Ah[0], ah1 = Ah[8 * SA_S], ah2 = Ah[4], ah3 = Ah[8 * SA_S + 4];
            uint32_t al0 = Al[0], al1 = Al[8 * SA_S], al2 = Al[4], al3 = Al[8 * SA_S + 4];

            const uint4* Brow = Bf + ((kt * 8 + ks) * 8 + wn * 4) * 32 + lane;
#pragma unroll
            for (int nt = 0; nt < 4; nt++) {
                uint4 b = __ldg(Brow + nt * 32);
                mma_tf32(c[nt], ah0, ah1, ah2, ah3, b.x, b.y);
                mma_tf32(c[nt], ah0, ah1, ah2, ah3, b.z, b.w);
                mma_tf32(c[nt], al0, al1, al2, al3, b.x, b.y);
            }
        }
        if (kt == 0) __syncthreads();   // last half: no smem reuse follows
    }

    // Epilogue: c0 (row=g, col=t4*2), c1 (col+1), c2 (row+8), c3 (row+8,col+1).
#pragma unroll
    for (int nt = 0; nt < 4; nt++) {
        int col = wn * 32 + nt * 8 + t4 * 2;
        float b0 = bias[col];
        float b1 = bias[col + 1];
        int row0 = m0 + wm * 16 + g;
        int row1 = row0 + 8;
        float2 o0 = make_float2(c[nt][0] + b0, c[nt][1] + b1);
        float2 o1 = make_float2(c[nt][2] + b0, c[nt][3] + b1);
        if (doRelu) {
            o0.x = fmaxf(o0.x, 0.f); o0.y = fmaxf(o0.y, 0.f);
            o1.x = fmaxf(o1.x, 0.f); o1.y = fmaxf(o1.y, 0.f);
        }
        if (row0 < NN)
            *reinterpret_cast<float2*>(outp + (size_t)row0 * DD + col) = o0;
        if (row1 < NN)
            *reinterpret_cast<float2*>(outp + (size_t)row1 * DD + col) = o1;
    }
}

extern "C" void kernel_launch(void* const* d_in, const int* in_sizes, int n_in,
                              void* d_out, int out_size) {
    const float* x        = (const float*)d_in[0];
    const void* ei        = d_in[1];
    const float* Wl0      = (const float*)d_in[2];
    const float* bl0      = (const float*)d_in[3];
    const float* Wr0      = (const float*)d_in[4];
    const float* Wl1      = (const float*)d_in[5];
    const float* bl1      = (const float*)d_in[6];
    const float* Wr1      = (const float*)d_in[7];
    float* out = (float*)d_out;

    int E = in_sizes[1] / 2;

    int edgeBlocks = (E + 255) / 256;
    int aggBlocks = (NN * 16 + 255) / 256;
    int gemmBlocks = (NN + 63) / 64;

    setup_kernel<<<(NN + 255) / 256, 256>>>(Wl0, Wr0, Wl1, Wr1, (const long long*)ei);

    // CSR build (shared by both layers)
    convert_count<<<edgeBlocks, 256>>>(ei, E);
    scan1<<<NBLK, SCAN_B>>>();
    fill_csr<<<edgeBlocks, 256>>>(E);

    // Layer 0
    aggregate<<<aggBlocks, 256>>>(x, /*useH=*/0);
    gemm_combine<<<gemmBlocks, 256>>>(x, /*useH=*/0, /*useW1=*/0, bl0, out,
                                      /*writeH=*/1, /*doRelu=*/1);

    // Layer 1
    aggregate<<<aggBlocks, 256>>>(x, /*useH=*/1);
    gemm_combine<<<gemmBlocks, 256>>>(x, /*useH=*/1, /*useW1=*/1, bl1, out,
                                      /*writeH=*/0, /*doRelu=*/0);
}